// round 2
// baseline (speedup 1.0000x reference)
#include <cuda_runtime.h>

#define BATCH 2
#define SEQ   2048
#define EMB   512
#define NHEAD 8
#define HDIM  64
#define M1    (BATCH * SEQ)     // 4096
#define N1    (3 * EMB)         // 1536
#define KD    EMB               // 512
#define ATT_SCALE 0.125f        // 64^-0.5

// Scratch (allocation-free: __device__ globals)
__device__ float g_qkv[M1 * N1];   // [b*s, 3E] natural layout
__device__ float g_att[M1 * EMB];  // attention output, [b*s, E]

// ---------------------------------------------------------------------------
// SGEMM: C[M,N] = A[M,K] @ B[K,N] (+bias). BM=BN=128, BK=8, 256 threads,
// 8x8 accumulators per thread. M%128==0, N%128==0, K%8==0 hold for all calls.
// ---------------------------------------------------------------------------
__device__ __forceinline__ void sgemm_body(const float* __restrict__ A,
                                           const float* __restrict__ Bm,
                                           float* __restrict__ C,
                                           int M, int N, int K,
                                           const float* __restrict__ bias)
{
    __shared__ float As[8][128];
    __shared__ float Bs[8][128];

    const int tid  = threadIdx.x;
    const int arow = tid >> 1;          // 0..127
    const int acol = (tid & 1) * 4;     // 0 or 4
    const int brL  = tid >> 5;          // 0..7
    const int bcL  = (tid & 31) * 4;    // 0..124
    const int ty   = tid >> 4;          // 0..15
    const int tx   = tid & 15;          // 0..15

    const float* Ab = A  + (size_t)blockIdx.y * 128 * K;
    const float* Bb = Bm + (size_t)blockIdx.x * 128;

    float acc[8][8];
    #pragma unroll
    for (int i = 0; i < 8; i++)
        #pragma unroll
        for (int j = 0; j < 8; j++) acc[i][j] = 0.f;

    for (int k0 = 0; k0 < K; k0 += 8) {
        float4 a4 = *(const float4*)(Ab + (size_t)arow * K + k0 + acol);
        As[acol + 0][arow] = a4.x;
        As[acol + 1][arow] = a4.y;
        As[acol + 2][arow] = a4.z;
        As[acol + 3][arow] = a4.w;
        float4 b4 = *(const float4*)(Bb + (size_t)(k0 + brL) * N + bcL);
        *(float4*)(&Bs[brL][bcL]) = b4;
        __syncthreads();

        #pragma unroll
        for (int kk = 0; kk < 8; kk++) {
            float ar[8], br[8];
            #pragma unroll
            for (int i = 0; i < 8; i++) ar[i] = As[kk][ty * 8 + i];
            #pragma unroll
            for (int j = 0; j < 8; j++) br[j] = Bs[kk][tx * 8 + j];
            #pragma unroll
            for (int i = 0; i < 8; i++)
                #pragma unroll
                for (int j = 0; j < 8; j++)
                    acc[i][j] = fmaf(ar[i], br[j], acc[i][j]);
        }
        __syncthreads();
    }

    #pragma unroll
    for (int i = 0; i < 8; i++) {
        int r = blockIdx.y * 128 + ty * 8 + i;
        #pragma unroll
        for (int j = 0; j < 8; j += 4) {
            int c = blockIdx.x * 128 + tx * 8 + j;
            float4 v = make_float4(acc[i][j], acc[i][j+1], acc[i][j+2], acc[i][j+3]);
            if (bias) {
                v.x += bias[c + 0]; v.y += bias[c + 1];
                v.z += bias[c + 2]; v.w += bias[c + 3];
            }
            *(float4*)(C + (size_t)r * N + c) = v;
        }
    }
}

__global__ __launch_bounds__(256) void gemm_qkv_kernel(const float* __restrict__ x,
                                                       const float* __restrict__ w)
{
    sgemm_body(x, w, g_qkv, M1, N1, KD, nullptr);
}

__global__ __launch_bounds__(256) void gemm_out_kernel(const float* __restrict__ w,
                                                       const float* __restrict__ bias,
                                                       float* __restrict__ out)
{
    sgemm_body(g_att, w, out, M1, EMB, EMB, bias);
}

// ---------------------------------------------------------------------------
// Flash-style attention. grid = (SEQ/128, NHEAD, BATCH), 128 threads.
// Each thread owns one q row (q and o accumulator in registers),
// K/V streamed through smem in tiles of 64 keys, online softmax per 16-key
// chunk.
// ---------------------------------------------------------------------------
__global__ __launch_bounds__(128) void attn_kernel()
{
    __shared__ float Ks[64][64];
    __shared__ float Vs[64][64];

    const int r    = threadIdx.x;
    const int qrow = blockIdx.x * 128 + r;
    const int h    = blockIdx.y;
    const int b    = blockIdx.z;

    // Load q row (pre-scaled)
    const float* qp = g_qkv + ((size_t)(b * SEQ + qrow)) * N1 + h * HDIM;
    float q[HDIM];
    #pragma unroll
    for (int d = 0; d < HDIM; d += 4) {
        float4 v = *(const float4*)(qp + d);
        q[d + 0] = v.x * ATT_SCALE; q[d + 1] = v.y * ATT_SCALE;
        q[d + 2] = v.z * ATT_SCALE; q[d + 3] = v.w * ATT_SCALE;
    }

    float o[HDIM];
    #pragma unroll
    for (int d = 0; d < HDIM; d++) o[d] = 0.f;
    float m = -1e30f;
    float l = 0.f;

    for (int t = 0; t < SEQ / 64; t++) {
        // Cooperative load of 64 keys + values (K at +EMB, V at +2*EMB).
        // 64 rows x 16 float4 per buffer = 1024 float4 -> 8 iters of 128 thr.
        const float* kb = g_qkv + ((size_t)(b * SEQ + t * 64)) * N1 + EMB + h * HDIM;
        #pragma unroll
        for (int i = 0; i < 8; i++) {
            int f   = r + i * 128;         // 0..1023
            int row = f >> 4;              // 0..63
            int c4  = (f & 15) * 4;        // 0..60
            const float* src = kb + (size_t)row * N1 + c4;
            *(float4*)(&Ks[row][c4]) = *(const float4*)(src);
            *(float4*)(&Vs[row][c4]) = *(const float4*)(src + EMB);
        }
        __syncthreads();

        #pragma unroll
        for (int c = 0; c < 4; c++) {          // 16-key chunks
            float s[16];
            float cm = -1e30f;
            #pragma unroll
            for (int j = 0; j < 16; j++) {
                const float* kp = &Ks[c * 16 + j][0];
                float a = 0.f;
                #pragma unroll
                for (int d = 0; d < HDIM; d += 4) {
                    float4 k4 = *(const float4*)(kp + d);
                    a = fmaf(q[d + 0], k4.x, a);
                    a = fmaf(q[d + 1], k4.y, a);
                    a = fmaf(q[d + 2], k4.z, a);
                    a = fmaf(q[d + 3], k4.w, a);
                }
                s[j] = a;
                cm = fmaxf(cm, a);
            }
            float mn = fmaxf(m, cm);
            float corr = __expf(m - mn);
            m = mn;
            l *= corr;
            #pragma unroll
            for (int d = 0; d < HDIM; d++) o[d] *= corr;
            #pragma unroll
            for (int j = 0; j < 16; j++) {
                float p = __expf(s[j] - m);
                l += p;
                const float* vp = &Vs[c * 16 + j][0];
                #pragma unroll
                for (int d = 0; d < HDIM; d += 4) {
                    float4 v4 = *(const float4*)(vp + d);
                    o[d + 0] = fmaf(p, v4.x, o[d + 0]);
                    o[d + 1] = fmaf(p, v4.y, o[d + 1]);
                    o[d + 2] = fmaf(p, v4.z, o[d + 2]);
                    o[d + 3] = fmaf(p, v4.w, o[d + 3]);
                }
            }
        }
        __syncthreads();
    }

    float inv = 1.f / l;
    float* op = g_att + ((size_t)(b * SEQ + qrow)) * EMB + h * HDIM;
    #pragma unroll
    for (int d = 0; d < HDIM; d += 4) {
        float4 v = make_float4(o[d] * inv, o[d+1] * inv, o[d+2] * inv, o[d+3] * inv);
        *(float4*)(op + d) = v;
    }
}

// ---------------------------------------------------------------------------
extern "C" void kernel_launch(void* const* d_in, const int* in_sizes, int n_in,
                              void* d_out, int out_size)
{
    const float* x     = (const float*)d_in[0];
    const float* w_qkv = (const float*)d_in[1];
    const float* w_o   = (const float*)d_in[2];
    const float* b_o   = (const float*)d_in[3];
    float* out = (float*)d_out;

    gemm_qkv_kernel<<<dim3(N1 / 128, M1 / 128), 256>>>(x, w_qkv);
    attn_kernel<<<dim3(SEQ / 128, NHEAD, BATCH), 128>>>();
    gemm_out_kernel<<<dim3(EMB / 128, M1 / 128), 256>>>(w_o, b_o, out);
}

// round 6
// speedup vs baseline: 4.2448x; 4.2448x over previous
#include <cuda_runtime.h>
#include <cuda_bf16.h>
#include <cstdint>

#define BATCH 2
#define SEQ   2048
#define EMB   512
#define NHEAD 8
#define HDIM  64
#define M1    (BATCH * SEQ)     // 4096
#define N1    (3 * EMB)         // 1536
#define KD    EMB               // 512
#define ATT_SCALE 0.125f

// ---------------------------------------------------------------------------
// helpers
// ---------------------------------------------------------------------------
__device__ __forceinline__ uint32_t smem_u32(const void* p) {
    uint32_t a;
    asm("{ .reg .u64 t; cvta.to.shared.u64 t, %1; cvt.u32.u64 %0, t; }" : "=r"(a) : "l"(p));
    return a;
}
__device__ __forceinline__ void ldsm4(uint32_t addr, uint32_t& r0, uint32_t& r1,
                                      uint32_t& r2, uint32_t& r3) {
    asm volatile("ldmatrix.sync.aligned.m8n8.x4.shared.b16 {%0,%1,%2,%3}, [%4];"
                 : "=r"(r0), "=r"(r1), "=r"(r2), "=r"(r3) : "r"(addr));
}
__device__ __forceinline__ void mma16816(float* c, uint32_t a0, uint32_t a1,
                                         uint32_t a2, uint32_t a3,
                                         uint32_t b0, uint32_t b1) {
    asm volatile("mma.sync.aligned.m16n8k16.row.col.f32.bf16.bf16.f32 "
                 "{%0,%1,%2,%3}, {%4,%5,%6,%7}, {%8,%9}, {%0,%1,%2,%3};"
                 : "+f"(c[0]), "+f"(c[1]), "+f"(c[2]), "+f"(c[3])
                 : "r"(a0), "r"(a1), "r"(a2), "r"(a3), "r"(b0), "r"(b1));
}
__device__ __forceinline__ void split2(float v, __nv_bfloat16& h, __nv_bfloat16& l) {
    h = __float2bfloat16(v);
    l = __float2bfloat16(v - __bfloat162float(h));
}
__device__ __forceinline__ uint32_t pack2(__nv_bfloat16 x, __nv_bfloat16 y) {
    __nv_bfloat162 t; t.x = x; t.y = y;
    return *(uint32_t*)&t;
}
// A-operand 16x16 ldmatrix.x4 address (rows = m, cols = k, row-major, stride bytes)
__device__ __forceinline__ uint32_t a_addr(uint32_t base, int r0, int c0, int lane, int stride) {
    return base + (uint32_t)(r0 + (lane & 15)) * stride + (uint32_t)(c0 + ((lane >> 4) << 3)) * 2;
}
// B-operand ldmatrix.x4 address (smem rows = n, cols = k)
__device__ __forceinline__ uint32_t b_addr(uint32_t base, int n0, int c0, int lane, int stride) {
    int n = n0 + (lane & 7) + ((lane >> 4) << 3);
    int k = c0 + (((lane >> 3) & 1) << 3);
    return base + (uint32_t)n * stride + (uint32_t)k * 2;
}

// ---------------------------------------------------------------------------
// Scratch (bf16 hi/lo pairs)
// ---------------------------------------------------------------------------
__device__ __nv_bfloat16 g_Xh[M1 * KD],  g_Xl[M1 * KD];
__device__ __nv_bfloat16 g_Wqh[N1 * KD], g_Wql[N1 * KD];       // w_qkv^T [N,K]
__device__ __nv_bfloat16 g_Woh[EMB * EMB], g_Wol[EMB * EMB];   // w_o^T   [N,K]
__device__ __nv_bfloat16 g_Qh[BATCH*NHEAD*SEQ*HDIM], g_Ql[BATCH*NHEAD*SEQ*HDIM];
__device__ __nv_bfloat16 g_Kh[BATCH*NHEAD*SEQ*HDIM], g_Kl[BATCH*NHEAD*SEQ*HDIM];
__device__ __nv_bfloat16 g_Vth[BATCH*NHEAD*HDIM*SEQ], g_Vtl[BATCH*NHEAD*HDIM*SEQ];
__device__ __nv_bfloat16 g_Ah[M1 * EMB], g_Al[M1 * EMB];

// ---------------------------------------------------------------------------
__global__ __launch_bounds__(256) void split_kernel(const float* __restrict__ in,
                                                    __nv_bfloat16* __restrict__ h,
                                                    __nv_bfloat16* __restrict__ l, int n)
{
    int i = blockIdx.x * 256 + threadIdx.x;
    if (i < n) { __nv_bfloat16 a, b; split2(in[i], a, b); h[i] = a; l[i] = b; }
}
__global__ __launch_bounds__(256) void tsplit_kernel(const float* __restrict__ in,
                                                     __nv_bfloat16* __restrict__ h,
                                                     __nv_bfloat16* __restrict__ l,
                                                     int K, int N)
{
    int i = blockIdx.x * 256 + threadIdx.x;
    if (i < K * N) {
        int k = i / N, n = i - k * N;
        __nv_bfloat16 a, b; split2(in[i], a, b);
        h[(size_t)n * K + k] = a; l[(size_t)n * K + k] = b;
    }
}

// ---------------------------------------------------------------------------
// GEMM mainloop: acc[2][8][4] += A[m0:+128, :] @ B[n0:+128, :]^T (bf16x3)
// 256 threads, warps 4x2 (wm 32 rows, wn 64 cols). BK=64, smem stride 144B.
// ---------------------------------------------------------------------------
#define GSTR 144
#define G_AH 0
#define G_AL 18432
#define G_BH 36864
#define G_BL 55296
#define G_SMEM_SZ 73728

__device__ __forceinline__ void gemm_mainloop(char* smem, uint32_t sb,
    const __nv_bfloat16* __restrict__ Ah, const __nv_bfloat16* __restrict__ Al,
    const __nv_bfloat16* __restrict__ Bh, const __nv_bfloat16* __restrict__ Bl,
    int Kdim, int m0, int n0, float acc[2][8][4])
{
    const int tid  = threadIdx.x;
    const int warp = tid >> 5, lane = tid & 31;
    const int wm = warp & 3, wn = warp >> 2;

    for (int k0 = 0; k0 < Kdim; k0 += 64) {
        #pragma unroll
        for (int i = 0; i < 4; i++) {
            int idx = tid + i * 256;
            int row = idx >> 3, q = idx & 7;
            uint32_t so = (uint32_t)row * GSTR + q * 16;
            size_t asrc = (size_t)(m0 + row) * Kdim + k0 + q * 8;
            size_t bsrc = (size_t)(n0 + row) * Kdim + k0 + q * 8;
            *(uint4*)(smem + G_AH + so) = *(const uint4*)(Ah + asrc);
            *(uint4*)(smem + G_AL + so) = *(const uint4*)(Al + asrc);
            *(uint4*)(smem + G_BH + so) = *(const uint4*)(Bh + bsrc);
            *(uint4*)(smem + G_BL + so) = *(const uint4*)(Bl + bsrc);
        }
        __syncthreads();

        #pragma unroll
        for (int kk = 0; kk < 4; kk++) {
            uint32_t ah[2][4], al[2][4];
            #pragma unroll
            for (int mi = 0; mi < 2; mi++) {
                ldsm4(a_addr(sb + G_AH, wm * 32 + mi * 16, kk * 16, lane, GSTR),
                      ah[mi][0], ah[mi][1], ah[mi][2], ah[mi][3]);
                ldsm4(a_addr(sb + G_AL, wm * 32 + mi * 16, kk * 16, lane, GSTR),
                      al[mi][0], al[mi][1], al[mi][2], al[mi][3]);
            }
            #pragma unroll
            for (int njp = 0; njp < 4; njp++) {
                uint32_t bh[4], bl[4];
                ldsm4(b_addr(sb + G_BH, wn * 64 + njp * 16, kk * 16, lane, GSTR),
                      bh[0], bh[1], bh[2], bh[3]);
                ldsm4(b_addr(sb + G_BL, wn * 64 + njp * 16, kk * 16, lane, GSTR),
                      bl[0], bl[1], bl[2], bl[3]);
                #pragma unroll
                for (int mi = 0; mi < 2; mi++) {
                    float* c0 = acc[mi][2 * njp];
                    float* c1 = acc[mi][2 * njp + 1];
                    mma16816(c0, ah[mi][0], ah[mi][1], ah[mi][2], ah[mi][3], bh[0], bh[1]);
                    mma16816(c0, al[mi][0], al[mi][1], al[mi][2], al[mi][3], bh[0], bh[1]);
                    mma16816(c0, ah[mi][0], ah[mi][1], ah[mi][2], ah[mi][3], bl[0], bl[1]);
                    mma16816(c1, ah[mi][0], ah[mi][1], ah[mi][2], ah[mi][3], bh[2], bh[3]);
                    mma16816(c1, al[mi][0], al[mi][1], al[mi][2], al[mi][3], bh[2], bh[3]);
                    mma16816(c1, ah[mi][0], ah[mi][1], ah[mi][2], ah[mi][3], bl[2], bl[3]);
                }
            }
        }
        __syncthreads();
    }
}

// ---------------------------------------------------------------------------
// QKV GEMM + scatter epilogue. grid (12, 32)
// ---------------------------------------------------------------------------
__global__ __launch_bounds__(256) void gemm_qkv_tc()
{
    extern __shared__ char smem[];
    uint32_t sb = smem_u32(smem);
    const int warp = threadIdx.x >> 5, lane = threadIdx.x & 31;
    const int wm = warp & 3, wn = warp >> 2;
    const int m0 = blockIdx.y * 128, n0 = blockIdx.x * 128;

    float acc[2][8][4];
    #pragma unroll
    for (int a = 0; a < 2; a++)
        #pragma unroll
        for (int b = 0; b < 8; b++)
            #pragma unroll
            for (int c = 0; c < 4; c++) acc[a][b][c] = 0.f;

    gemm_mainloop(smem, sb, g_Xh, g_Xl, g_Wqh, g_Wql, KD, m0, n0, acc);

    const int region = n0 >> 9;  // 0=Q 1=K 2=V
    #pragma unroll
    for (int mi = 0; mi < 2; mi++) {
        #pragma unroll
        for (int ri = 0; ri < 2; ri++) {
            int r = m0 + wm * 32 + mi * 16 + (lane >> 2) + ri * 8;
            int b = r >> 11, s = r & 2047;
            #pragma unroll
            for (int nj = 0; nj < 8; nj++) {
                int c = n0 + wn * 64 + nj * 8 + (lane & 3) * 2;
                int within = c & 511;
                int h = within >> 6, dd = within & 63;
                float v0 = acc[mi][nj][ri * 2 + 0];
                float v1 = acc[mi][nj][ri * 2 + 1];
                if (region == 0) { v0 *= ATT_SCALE; v1 *= ATT_SCALE; }
                __nv_bfloat16 h0, l0, h1, l1;
                split2(v0, h0, l0); split2(v1, h1, l1);
                if (region < 2) {
                    __nv_bfloat16* H = region == 0 ? g_Qh : g_Kh;
                    __nv_bfloat16* L = region == 0 ? g_Ql : g_Kl;
                    size_t idx = (((size_t)(b * NHEAD + h) * SEQ + s) * HDIM + dd);
                    *(uint32_t*)(H + idx) = pack2(h0, h1);
                    *(uint32_t*)(L + idx) = pack2(l0, l1);
                } else {
                    size_t base = ((size_t)(b * NHEAD + h) * HDIM + dd) * SEQ + s;
                    g_Vth[base] = h0;       g_Vtl[base] = l0;
                    g_Vth[base + SEQ] = h1; g_Vtl[base + SEQ] = l1;
                }
            }
        }
    }
}

// ---------------------------------------------------------------------------
// Out projection + bias. grid (4, 32)
// ---------------------------------------------------------------------------
__global__ __launch_bounds__(256) void gemm_out_tc(const float* __restrict__ bias,
                                                   float* __restrict__ out)
{
    extern __shared__ char smem[];
    uint32_t sb = smem_u32(smem);
    const int warp = threadIdx.x >> 5, lane = threadIdx.x & 31;
    const int wm = warp & 3, wn = warp >> 2;
    const int m0 = blockIdx.y * 128, n0 = blockIdx.x * 128;

    float acc[2][8][4];
    #pragma unroll
    for (int a = 0; a < 2; a++)
        #pragma unroll
        for (int b = 0; b < 8; b++)
            #pragma unroll
            for (int c = 0; c < 4; c++) acc[a][b][c] = 0.f;

    gemm_mainloop(smem, sb, g_Ah, g_Al, g_Woh, g_Wol, EMB, m0, n0, acc);

    #pragma unroll
    for (int mi = 0; mi < 2; mi++) {
        #pragma unroll
        for (int ri = 0; ri < 2; ri++) {
            int r = m0 + wm * 32 + mi * 16 + (lane >> 2) + ri * 8;
            #pragma unroll
            for (int nj = 0; nj < 8; nj++) {
                int c = n0 + wn * 64 + nj * 8 + (lane & 3) * 2;
                float2 v;
                v.x = acc[mi][nj][ri * 2 + 0] + bias[c];
                v.y = acc[mi][nj][ri * 2 + 1] + bias[c + 1];
                *(float2*)(out + (size_t)r * EMB + c) = v;
            }
        }
    }
}

// ---------------------------------------------------------------------------
// Flash attention. grid (16 qtiles, 16 bh), 256 threads.
// Warp w owns S rows w*16..w*16+15; softmax row stats reduced across the quad
// (shfl_xor 1,2) for BOTH max and sum.
// ---------------------------------------------------------------------------
#define PSTR 272
#define A_PH 0
#define A_PL 34816
#define A_KH 69632
#define A_KL 88064
#define A_VH 106496
#define A_VL 123904
#define A_SMEM_SZ 141312

__global__ __launch_bounds__(256) void attn_tc()
{
    extern __shared__ char smem[];
    uint32_t sb = smem_u32(smem);
    const int tid = threadIdx.x;
    const int warp = tid >> 5, lane = tid & 31;
    const int bh = blockIdx.y;
    const int q0 = blockIdx.x * 128;
    const size_t qk_base = (size_t)bh * SEQ * HDIM;

    // Stage Q (hi/lo) into P region (stride GSTR), hoist fragments to registers
    #pragma unroll
    for (int i = 0; i < 4; i++) {
        int idx = tid + i * 256;
        int row = idx >> 3, q = idx & 7;
        uint32_t so = (uint32_t)row * GSTR + q * 16;
        size_t src = qk_base + (size_t)(q0 + row) * HDIM + q * 8;
        *(uint4*)(smem + A_PH + so) = *(const uint4*)(g_Qh + src);
        *(uint4*)(smem + A_PL + so) = *(const uint4*)(g_Ql + src);
    }
    __syncthreads();
    uint32_t qh[4][4], ql[4][4];
    #pragma unroll
    for (int kk = 0; kk < 4; kk++) {
        ldsm4(a_addr(sb + A_PH, warp * 16, kk * 16, lane, GSTR),
              qh[kk][0], qh[kk][1], qh[kk][2], qh[kk][3]);
        ldsm4(a_addr(sb + A_PL, warp * 16, kk * 16, lane, GSTR),
              ql[kk][0], ql[kk][1], ql[kk][2], ql[kk][3]);
    }
    __syncthreads();   // everyone done reading Q; P region reusable

    float o[8][4];
    #pragma unroll
    for (int a = 0; a < 8; a++)
        #pragma unroll
        for (int c = 0; c < 4; c++) o[a][c] = 0.f;
    float m[2] = {-1e30f, -1e30f};
    float lsum[2] = {0.f, 0.f};

    for (int t = 0; t < SEQ / 128; t++) {
        // load K (hi/lo, [key][d], 144B stride) and Vt (hi/lo, [d][key], 272B stride)
        #pragma unroll
        for (int i = 0; i < 4; i++) {
            int idx = tid + i * 256;
            { int row = idx >> 3, q = idx & 7;
              uint32_t so = (uint32_t)row * GSTR + q * 16;
              size_t src = qk_base + (size_t)(t * 128 + row) * HDIM + q * 8;
              *(uint4*)(smem + A_KH + so) = *(const uint4*)(g_Kh + src);
              *(uint4*)(smem + A_KL + so) = *(const uint4*)(g_Kl + src); }
            { int row = idx >> 4, q = idx & 15;
              uint32_t so = (uint32_t)row * PSTR + q * 16;
              size_t src = qk_base + (size_t)row * SEQ + t * 128 + q * 8;
              *(uint4*)(smem + A_VH + so) = *(const uint4*)(g_Vth + src);
              *(uint4*)(smem + A_VL + so) = *(const uint4*)(g_Vtl + src); }
        }
        __syncthreads();

        // S = Q K^T (bf16x3), rows warp*16..+15, all 128 key cols
        float sc[16][4];
        #pragma unroll
        for (int a = 0; a < 16; a++)
            #pragma unroll
            for (int c = 0; c < 4; c++) sc[a][c] = 0.f;

        #pragma unroll
        for (int kk = 0; kk < 4; kk++) {
            #pragma unroll
            for (int njp = 0; njp < 8; njp++) {
                uint32_t bh4[4], bl4[4];
                ldsm4(b_addr(sb + A_KH, njp * 16, kk * 16, lane, GSTR), bh4[0], bh4[1], bh4[2], bh4[3]);
                ldsm4(b_addr(sb + A_KL, njp * 16, kk * 16, lane, GSTR), bl4[0], bl4[1], bl4[2], bl4[3]);
                float* c0 = sc[2 * njp];
                float* c1 = sc[2 * njp + 1];
                mma16816(c0, qh[kk][0], qh[kk][1], qh[kk][2], qh[kk][3], bh4[0], bh4[1]);
                mma16816(c0, ql[kk][0], ql[kk][1], ql[kk][2], ql[kk][3], bh4[0], bh4[1]);
                mma16816(c0, qh[kk][0], qh[kk][1], qh[kk][2], qh[kk][3], bl4[0], bl4[1]);
                mma16816(c1, qh[kk][0], qh[kk][1], qh[kk][2], qh[kk][3], bh4[2], bh4[3]);
                mma16816(c1, ql[kk][0], ql[kk][1], ql[kk][2], ql[kk][3], bh4[2], bh4[3]);
                mma16816(c1, qh[kk][0], qh[kk][1], qh[kk][2], qh[kk][3], bl4[2], bl4[3]);
            }
        }

        // online softmax; rows r = lane>>2 (ri=0) and r+8 (ri=1)
        float mx[2] = {-1e30f, -1e30f};
        #pragma unroll
        for (int nj = 0; nj < 16; nj++) {
            mx[0] = fmaxf(mx[0], fmaxf(sc[nj][0], sc[nj][1]));
            mx[1] = fmaxf(mx[1], fmaxf(sc[nj][2], sc[nj][3]));
        }
        #pragma unroll
        for (int ri = 0; ri < 2; ri++) {
            mx[ri] = fmaxf(mx[ri], __shfl_xor_sync(0xffffffff, mx[ri], 1));
            mx[ri] = fmaxf(mx[ri], __shfl_xor_sync(0xffffffff, mx[ri], 2));
        }
        float corr[2];
        #pragma unroll
        for (int ri = 0; ri < 2; ri++) {
            float nm = fmaxf(m[ri], mx[ri]);
            corr[ri] = __expf(m[ri] - nm);
            m[ri] = nm;
        }

        // exp + split + write P strip to smem (warp-private rows)
        const int g = lane >> 2;
        const uint32_t pcol = (uint32_t)((lane & 3) * 2) * 2;
        const uint32_t prow0 = (uint32_t)(warp * 16 + g) * PSTR;
        float ls[2] = {0.f, 0.f};
        #pragma unroll
        for (int nj = 0; nj < 16; nj++) {
            float p0 = __expf(sc[nj][0] - m[0]);
            float p1 = __expf(sc[nj][1] - m[0]);
            float p2 = __expf(sc[nj][2] - m[1]);
            float p3 = __expf(sc[nj][3] - m[1]);
            ls[0] += p0 + p1; ls[1] += p2 + p3;
            __nv_bfloat16 a0, b0, a1, b1, a2, b2, a3, b3;
            split2(p0, a0, b0); split2(p1, a1, b1);
            split2(p2, a2, b2); split2(p3, a3, b3);
            uint32_t coff = (uint32_t)(nj * 8) * 2 + pcol;
            *(uint32_t*)(smem + A_PH + prow0 + coff)            = pack2(a0, a1);
            *(uint32_t*)(smem + A_PL + prow0 + coff)            = pack2(b0, b1);
            *(uint32_t*)(smem + A_PH + prow0 + 8 * PSTR + coff) = pack2(a2, a3);
            *(uint32_t*)(smem + A_PL + prow0 + 8 * PSTR + coff) = pack2(b2, b3);
        }
        __syncwarp();
        // *** THE FIX: reduce row-sum across the quad (each lane held 32/128 cols) ***
        #pragma unroll
        for (int ri = 0; ri < 2; ri++) {
            ls[ri] += __shfl_xor_sync(0xffffffff, ls[ri], 1);
            ls[ri] += __shfl_xor_sync(0xffffffff, ls[ri], 2);
        }
        lsum[0] = lsum[0] * corr[0] + ls[0];
        lsum[1] = lsum[1] * corr[1] + ls[1];
        #pragma unroll
        for (int nj = 0; nj < 8; nj++) {
            o[nj][0] *= corr[0]; o[nj][1] *= corr[0];
            o[nj][2] *= corr[1]; o[nj][3] *= corr[1];
        }

        // O += P V (bf16x3): A via standard ldmatrix from P smem
        #pragma unroll
        for (int kk = 0; kk < 8; kk++) {
            uint32_t ah4[4], al4[4];
            ldsm4(a_addr(sb + A_PH, warp * 16, kk * 16, lane, PSTR),
                  ah4[0], ah4[1], ah4[2], ah4[3]);
            ldsm4(a_addr(sb + A_PL, warp * 16, kk * 16, lane, PSTR),
                  al4[0], al4[1], al4[2], al4[3]);
            #pragma unroll
            for (int njp = 0; njp < 4; njp++) {
                uint32_t bh4[4], bl4[4];
                ldsm4(b_addr(sb + A_VH, njp * 16, kk * 16, lane, PSTR), bh4[0], bh4[1], bh4[2], bh4[3]);
                ldsm4(b_addr(sb + A_VL, njp * 16, kk * 16, lane, PSTR), bl4[0], bl4[1], bl4[2], bl4[3]);
                float* c0 = o[2 * njp];
                float* c1 = o[2 * njp + 1];
                mma16816(c0, ah4[0], ah4[1], ah4[2], ah4[3], bh4[0], bh4[1]);
                mma16816(c0, al4[0], al4[1], al4[2], al4[3], bh4[0], bh4[1]);
                mma16816(c0, ah4[0], ah4[1], ah4[2], ah4[3], bl4[0], bl4[1]);
                mma16816(c1, ah4[0], ah4[1], ah4[2], ah4[3], bh4[2], bh4[3]);
                mma16816(c1, al4[0], al4[1], al4[2], al4[3], bh4[2], bh4[3]);
                mma16816(c1, ah4[0], ah4[1], ah4[2], ah4[3], bl4[2], bl4[3]);
            }
        }
        __syncthreads();  // done with K/V/P smem before next tile overwrite
    }

    // epilogue: normalize + split-write to g_Ah/g_Al
    const int b = bh >> 3, h = bh & 7;
    float inv[2] = {1.f / lsum[0], 1.f / lsum[1]};
    #pragma unroll
    for (int ri = 0; ri < 2; ri++) {
        int r = q0 + warp * 16 + (lane >> 2) + ri * 8;
        size_t R = (size_t)(b * SEQ + r) * EMB + h * HDIM;
        #pragma unroll
        for (int nj = 0; nj < 8; nj++) {
            int dd = nj * 8 + (lane & 3) * 2;
            float v0 = o[nj][ri * 2 + 0] * inv[ri];
            float v1 = o[nj][ri * 2 + 1] * inv[ri];
            __nv_bfloat16 h0, l0, h1, l1;
            split2(v0, h0, l0); split2(v1, h1, l1);
            *(uint32_t*)(g_Ah + R + dd) = pack2(h0, h1);
            *(uint32_t*)(g_Al + R + dd) = pack2(l0, l1);
        }
    }
}

// ---------------------------------------------------------------------------
extern "C" void kernel_launch(void* const* d_in, const int* in_sizes, int n_in,
                              void* d_out, int out_size)
{
    const float* x     = (const float*)d_in[0];
    const float* w_qkv = (const float*)d_in[1];
    const float* w_o   = (const float*)d_in[2];
    const float* b_o   = (const float*)d_in[3];
    float* out = (float*)d_out;

    cudaFuncSetAttribute(gemm_qkv_tc, cudaFuncAttributeMaxDynamicSharedMemorySize, G_SMEM_SZ);
    cudaFuncSetAttribute(gemm_out_tc, cudaFuncAttributeMaxDynamicSharedMemorySize, G_SMEM_SZ);
    cudaFuncSetAttribute(attn_tc,     cudaFuncAttributeMaxDynamicSharedMemorySize, A_SMEM_SZ);

    __nv_bfloat16 *xh, *xl, *wqh, *wql, *woh, *wol;
    cudaGetSymbolAddress((void**)&xh,  g_Xh);  cudaGetSymbolAddress((void**)&xl,  g_Xl);
    cudaGetSymbolAddress((void**)&wqh, g_Wqh); cudaGetSymbolAddress((void**)&wql, g_Wql);
    cudaGetSymbolAddress((void**)&woh, g_Woh); cudaGetSymbolAddress((void**)&wol, g_Wol);

    split_kernel<<<(M1 * KD + 255) / 256, 256>>>(x, xh, xl, M1 * KD);
    tsplit_kernel<<<(KD * N1 + 255) / 256, 256>>>(w_qkv, wqh, wql, KD, N1);
    tsplit_kernel<<<(KD * EMB + 255) / 256, 256>>>(w_o, woh, wol, KD, EMB);

    gemm_qkv_tc<<<dim3(N1 / 128, M1 / 128), 256, G_SMEM_SZ>>>();
    attn_tc<<<dim3(SEQ / 128, BATCH * NHEAD), 256, A_SMEM_SZ>>>();
    gemm_out_tc<<<dim3(EMB / 128, M1 / 128), 256, G_SMEM_SZ>>>(b_o, out);
}

// round 7
// speedup vs baseline: 4.8652x; 1.1462x over previous
#include <cuda_runtime.h>
#include <cuda_bf16.h>
#include <cstdint>

#define BATCH 2
#define SEQ   2048
#define EMB   512
#define NHEAD 8
#define HDIM  64
#define M1    (BATCH * SEQ)     // 4096
#define N1    (3 * EMB)         // 1536
#define KD    EMB               // 512
#define ATT_SCALE 0.125f

// ---------------------------------------------------------------------------
// helpers
// ---------------------------------------------------------------------------
__device__ __forceinline__ uint32_t smem_u32(const void* p) {
    uint32_t a;
    asm("{ .reg .u64 t; cvta.to.shared.u64 t, %1; cvt.u32.u64 %0, t; }" : "=r"(a) : "l"(p));
    return a;
}
__device__ __forceinline__ void ldsm4(uint32_t addr, uint32_t& r0, uint32_t& r1,
                                      uint32_t& r2, uint32_t& r3) {
    asm volatile("ldmatrix.sync.aligned.m8n8.x4.shared.b16 {%0,%1,%2,%3}, [%4];"
                 : "=r"(r0), "=r"(r1), "=r"(r2), "=r"(r3) : "r"(addr));
}
__device__ __forceinline__ void mma16816(float* c, uint32_t a0, uint32_t a1,
                                         uint32_t a2, uint32_t a3,
                                         uint32_t b0, uint32_t b1) {
    asm volatile("mma.sync.aligned.m16n8k16.row.col.f32.bf16.bf16.f32 "
                 "{%0,%1,%2,%3}, {%4,%5,%6,%7}, {%8,%9}, {%0,%1,%2,%3};"
                 : "+f"(c[0]), "+f"(c[1]), "+f"(c[2]), "+f"(c[3])
                 : "r"(a0), "r"(a1), "r"(a2), "r"(a3), "r"(b0), "r"(b1));
}
__device__ __forceinline__ void cp16(uint32_t dst, const void* src) {
    asm volatile("cp.async.cg.shared.global [%0], [%1], 16;" :: "r"(dst), "l"(src));
}
#define CP_COMMIT() asm volatile("cp.async.commit_group;" ::: "memory")
#define CP_WAIT(n)  asm volatile("cp.async.wait_group %0;" :: "n"(n) : "memory")

__device__ __forceinline__ void split2(float v, __nv_bfloat16& h, __nv_bfloat16& l) {
    h = __float2bfloat16(v);
    l = __float2bfloat16(v - __bfloat162float(h));
}
__device__ __forceinline__ uint32_t pack2(__nv_bfloat16 x, __nv_bfloat16 y) {
    __nv_bfloat162 t; t.x = x; t.y = y;
    return *(uint32_t*)&t;
}
// A-operand 16x16 ldmatrix.x4 address (rows = m, cols = k, row-major, stride bytes)
__device__ __forceinline__ uint32_t a_addr(uint32_t base, int r0, int c0, int lane, int stride) {
    return base + (uint32_t)(r0 + (lane & 15)) * stride + (uint32_t)(c0 + ((lane >> 4) << 3)) * 2;
}
// B-operand ldmatrix.x4 address (smem rows = n, cols = k)
__device__ __forceinline__ uint32_t b_addr(uint32_t base, int n0, int c0, int lane, int stride) {
    int n = n0 + (lane & 7) + ((lane >> 4) << 3);
    int k = c0 + (((lane >> 3) & 1) << 3);
    return base + (uint32_t)n * stride + (uint32_t)k * 2;
}

// ---------------------------------------------------------------------------
// Scratch (bf16 hi/lo pairs)
// ---------------------------------------------------------------------------
__device__ __nv_bfloat16 g_Xh[M1 * KD],  g_Xl[M1 * KD];
__device__ __nv_bfloat16 g_Wqh[N1 * KD], g_Wql[N1 * KD];       // w_qkv^T [N,K]
__device__ __nv_bfloat16 g_Woh[EMB * EMB], g_Wol[EMB * EMB];   // w_o^T   [N,K]
__device__ __nv_bfloat16 g_Qh[BATCH*NHEAD*SEQ*HDIM], g_Ql[BATCH*NHEAD*SEQ*HDIM];
__device__ __nv_bfloat16 g_Kh[BATCH*NHEAD*SEQ*HDIM], g_Kl[BATCH*NHEAD*SEQ*HDIM];
__device__ __nv_bfloat16 g_Vth[BATCH*NHEAD*HDIM*SEQ], g_Vtl[BATCH*NHEAD*HDIM*SEQ];
__device__ __nv_bfloat16 g_Ah[M1 * EMB], g_Al[M1 * EMB];

// ---------------------------------------------------------------------------
__global__ __launch_bounds__(256) void split_kernel(const float* __restrict__ in,
                                                    __nv_bfloat16* __restrict__ h,
                                                    __nv_bfloat16* __restrict__ l, int n)
{
    int i = blockIdx.x * 256 + threadIdx.x;
    if (i < n) { __nv_bfloat16 a, b; split2(in[i], a, b); h[i] = a; l[i] = b; }
}
__global__ __launch_bounds__(256) void tsplit_kernel(const float* __restrict__ in,
                                                     __nv_bfloat16* __restrict__ h,
                                                     __nv_bfloat16* __restrict__ l,
                                                     int K, int N)
{
    int i = blockIdx.x * 256 + threadIdx.x;
    if (i < K * N) {
        int k = i / N, n = i - k * N;
        __nv_bfloat16 a, b; split2(in[i], a, b);
        h[(size_t)n * K + k] = a; l[(size_t)n * K + k] = b;
    }
}

// ---------------------------------------------------------------------------
// GEMM: acc[2][8][4] += A[m0:+128,:] @ B[n0:+128,:]^T (bf16x3), 2-stage cp.async
// 256 threads, warps 4x2. BK=64, smem stride 144B. Stage = 4 arrays x 18432B.
// ---------------------------------------------------------------------------
#define GSTR 144
#define G_AH 0
#define G_AL 18432
#define G_BH 36864
#define G_BL 55296
#define G_STAGE 73728
#define G_SMEM_SZ (2 * G_STAGE)

__device__ __forceinline__ void gemm_load_stage(uint32_t sbase,
    const __nv_bfloat16* Ah, const __nv_bfloat16* Al,
    const __nv_bfloat16* Bh, const __nv_bfloat16* Bl,
    int Kdim, int m0, int n0, int k0)
{
    const int tid = threadIdx.x;
    #pragma unroll
    for (int i = 0; i < 4; i++) {
        int idx = tid + i * 256;
        int row = idx >> 3, q = idx & 7;
        uint32_t so = (uint32_t)row * GSTR + q * 16;
        size_t asrc = (size_t)(m0 + row) * Kdim + k0 + q * 8;
        size_t bsrc = (size_t)(n0 + row) * Kdim + k0 + q * 8;
        cp16(sbase + G_AH + so, Ah + asrc);
        cp16(sbase + G_AL + so, Al + asrc);
        cp16(sbase + G_BH + so, Bh + bsrc);
        cp16(sbase + G_BL + so, Bl + bsrc);
    }
}

__device__ __forceinline__ void gemm_compute_stage(uint32_t sbase, int warp, int lane,
                                                   float acc[2][8][4])
{
    const int wm = warp & 3, wn = warp >> 2;
    #pragma unroll
    for (int kk = 0; kk < 4; kk++) {
        uint32_t ah[2][4], al[2][4];
        #pragma unroll
        for (int mi = 0; mi < 2; mi++) {
            ldsm4(a_addr(sbase + G_AH, wm * 32 + mi * 16, kk * 16, lane, GSTR),
                  ah[mi][0], ah[mi][1], ah[mi][2], ah[mi][3]);
            ldsm4(a_addr(sbase + G_AL, wm * 32 + mi * 16, kk * 16, lane, GSTR),
                  al[mi][0], al[mi][1], al[mi][2], al[mi][3]);
        }
        #pragma unroll
        for (int njp = 0; njp < 4; njp++) {
            uint32_t bh[4], bl[4];
            ldsm4(b_addr(sbase + G_BH, wn * 64 + njp * 16, kk * 16, lane, GSTR),
                  bh[0], bh[1], bh[2], bh[3]);
            ldsm4(b_addr(sbase + G_BL, wn * 64 + njp * 16, kk * 16, lane, GSTR),
                  bl[0], bl[1], bl[2], bl[3]);
            #pragma unroll
            for (int mi = 0; mi < 2; mi++) {
                float* c0 = acc[mi][2 * njp];
                float* c1 = acc[mi][2 * njp + 1];
                mma16816(c0, ah[mi][0], ah[mi][1], ah[mi][2], ah[mi][3], bh[0], bh[1]);
                mma16816(c0, al[mi][0], al[mi][1], al[mi][2], al[mi][3], bh[0], bh[1]);
                mma16816(c0, ah[mi][0], ah[mi][1], ah[mi][2], ah[mi][3], bl[0], bl[1]);
                mma16816(c1, ah[mi][0], ah[mi][1], ah[mi][2], ah[mi][3], bh[2], bh[3]);
                mma16816(c1, al[mi][0], al[mi][1], al[mi][2], al[mi][3], bh[2], bh[3]);
                mma16816(c1, ah[mi][0], ah[mi][1], ah[mi][2], ah[mi][3], bl[2], bl[3]);
            }
        }
    }
}

__device__ __forceinline__ void gemm_mainloop(uint32_t sb,
    const __nv_bfloat16* __restrict__ Ah, const __nv_bfloat16* __restrict__ Al,
    const __nv_bfloat16* __restrict__ Bh, const __nv_bfloat16* __restrict__ Bl,
    int Kdim, int m0, int n0, float acc[2][8][4])
{
    const int warp = threadIdx.x >> 5, lane = threadIdx.x & 31;
    const int nk = Kdim / 64;

    gemm_load_stage(sb, Ah, Al, Bh, Bl, Kdim, m0, n0, 0);
    CP_COMMIT();
    for (int kc = 0; kc < nk; kc++) {
        if (kc + 1 < nk) {
            gemm_load_stage(sb + ((kc + 1) & 1) * G_STAGE, Ah, Al, Bh, Bl,
                            Kdim, m0, n0, (kc + 1) * 64);
            CP_COMMIT();
            CP_WAIT(1);
        } else {
            CP_WAIT(0);
        }
        __syncthreads();
        gemm_compute_stage(sb + (kc & 1) * G_STAGE, warp, lane, acc);
        __syncthreads();
    }
}

// ---------------------------------------------------------------------------
// QKV GEMM + scatter epilogue. grid (12, 32)
// ---------------------------------------------------------------------------
__global__ __launch_bounds__(256) void gemm_qkv_tc()
{
    extern __shared__ char smem[];
    uint32_t sb = smem_u32(smem);
    const int warp = threadIdx.x >> 5, lane = threadIdx.x & 31;
    const int wm = warp & 3, wn = warp >> 2;
    const int m0 = blockIdx.y * 128, n0 = blockIdx.x * 128;

    float acc[2][8][4];
    #pragma unroll
    for (int a = 0; a < 2; a++)
        #pragma unroll
        for (int b = 0; b < 8; b++)
            #pragma unroll
            for (int c = 0; c < 4; c++) acc[a][b][c] = 0.f;

    gemm_mainloop(sb, g_Xh, g_Xl, g_Wqh, g_Wql, KD, m0, n0, acc);

    const int region = n0 >> 9;  // 0=Q 1=K 2=V
    #pragma unroll
    for (int mi = 0; mi < 2; mi++) {
        #pragma unroll
        for (int ri = 0; ri < 2; ri++) {
            int r = m0 + wm * 32 + mi * 16 + (lane >> 2) + ri * 8;
            int b = r >> 11, s = r & 2047;
            #pragma unroll
            for (int nj = 0; nj < 8; nj++) {
                int c = n0 + wn * 64 + nj * 8 + (lane & 3) * 2;
                int within = c & 511;
                int h = within >> 6, dd = within & 63;
                float v0 = acc[mi][nj][ri * 2 + 0];
                float v1 = acc[mi][nj][ri * 2 + 1];
                if (region == 0) { v0 *= ATT_SCALE; v1 *= ATT_SCALE; }
                __nv_bfloat16 h0, l0, h1, l1;
                split2(v0, h0, l0); split2(v1, h1, l1);
                if (region < 2) {
                    __nv_bfloat16* H = region == 0 ? g_Qh : g_Kh;
                    __nv_bfloat16* L = region == 0 ? g_Ql : g_Kl;
                    size_t idx = (((size_t)(b * NHEAD + h) * SEQ + s) * HDIM + dd);
                    *(uint32_t*)(H + idx) = pack2(h0, h1);
                    *(uint32_t*)(L + idx) = pack2(l0, l1);
                } else {
                    size_t base = ((size_t)(b * NHEAD + h) * HDIM + dd) * SEQ + s;
                    g_Vth[base] = h0;       g_Vtl[base] = l0;
                    g_Vth[base + SEQ] = h1; g_Vtl[base + SEQ] = l1;
                }
            }
        }
    }
}

// ---------------------------------------------------------------------------
// Out projection + bias. grid (4, 32)
// ---------------------------------------------------------------------------
__global__ __launch_bounds__(256) void gemm_out_tc(const float* __restrict__ bias,
                                                   float* __restrict__ out)
{
    extern __shared__ char smem[];
    uint32_t sb = smem_u32(smem);
    const int warp = threadIdx.x >> 5, lane = threadIdx.x & 31;
    const int wm = warp & 3, wn = warp >> 2;
    const int m0 = blockIdx.y * 128, n0 = blockIdx.x * 128;

    float acc[2][8][4];
    #pragma unroll
    for (int a = 0; a < 2; a++)
        #pragma unroll
        for (int b = 0; b < 8; b++)
            #pragma unroll
            for (int c = 0; c < 4; c++) acc[a][b][c] = 0.f;

    gemm_mainloop(sb, g_Ah, g_Al, g_Woh, g_Wol, EMB, m0, n0, acc);

    #pragma unroll
    for (int mi = 0; mi < 2; mi++) {
        #pragma unroll
        for (int ri = 0; ri < 2; ri++) {
            int r = m0 + wm * 32 + mi * 16 + (lane >> 2) + ri * 8;
            #pragma unroll
            for (int nj = 0; nj < 8; nj++) {
                int c = n0 + wn * 64 + nj * 8 + (lane & 3) * 2;
                float2 v;
                v.x = acc[mi][nj][ri * 2 + 0] + bias[c];
                v.y = acc[mi][nj][ri * 2 + 1] + bias[c + 1];
                *(float2*)(out + (size_t)r * EMB + c) = v;
            }
        }
    }
}

// ---------------------------------------------------------------------------
// Flash attention. grid (16 qtiles, 16 bh), 256 threads.
// Register P path (no smem round-trip; validated R3==R4) + 2-stage cp.async
// K/V prefetch. smem stage: KH/KL [128x72 bf16, 144B], VH/VL [64x136, 272B].
// ---------------------------------------------------------------------------
#define VSTR 272
#define A_KH 0
#define A_KL 18432
#define A_VH 36864
#define A_VL 54272
#define A_STAGE 71680
#define A_SMEM_SZ (2 * A_STAGE)

__device__ __forceinline__ void attn_load_stage(uint32_t sbase, size_t qk_base, int t)
{
    const int tid = threadIdx.x;
    #pragma unroll
    for (int i = 0; i < 4; i++) {
        int idx = tid + i * 256;
        { int row = idx >> 3, q = idx & 7;
          uint32_t so = (uint32_t)row * GSTR + q * 16;
          size_t src = qk_base + (size_t)(t * 128 + row) * HDIM + q * 8;
          cp16(sbase + A_KH + so, g_Kh + src);
          cp16(sbase + A_KL + so, g_Kl + src); }
        { int row = idx >> 4, q = idx & 15;
          uint32_t so = (uint32_t)row * VSTR + q * 16;
          size_t src = qk_base + (size_t)row * SEQ + t * 128 + q * 8;
          cp16(sbase + A_VH + so, g_Vth + src);
          cp16(sbase + A_VL + so, g_Vtl + src); }
    }
}

__global__ __launch_bounds__(256) void attn_tc()
{
    extern __shared__ char smem[];
    uint32_t sb = smem_u32(smem);
    const int tid = threadIdx.x;
    const int warp = tid >> 5, lane = tid & 31;
    const int bh = blockIdx.y;
    const int q0 = blockIdx.x * 128;
    const size_t qk_base = (size_t)bh * SEQ * HDIM;

    // Stage Q (hi/lo) into stage0 K region, hoist fragments, then free it.
    #pragma unroll
    for (int i = 0; i < 4; i++) {
        int idx = tid + i * 256;
        int row = idx >> 3, q = idx & 7;
        uint32_t so = (uint32_t)row * GSTR + q * 16;
        size_t src = qk_base + (size_t)(q0 + row) * HDIM + q * 8;
        *(uint4*)(smem + A_KH + so) = *(const uint4*)(g_Qh + src);
        *(uint4*)(smem + A_KL + so) = *(const uint4*)(g_Ql + src);
    }
    __syncthreads();
    uint32_t qh[4][4], ql[4][4];
    #pragma unroll
    for (int kk = 0; kk < 4; kk++) {
        ldsm4(a_addr(sb + A_KH, warp * 16, kk * 16, lane, GSTR),
              qh[kk][0], qh[kk][1], qh[kk][2], qh[kk][3]);
        ldsm4(a_addr(sb + A_KL, warp * 16, kk * 16, lane, GSTR),
              ql[kk][0], ql[kk][1], ql[kk][2], ql[kk][3]);
    }
    __syncthreads();

    float o[8][4];
    #pragma unroll
    for (int a = 0; a < 8; a++)
        #pragma unroll
        for (int c = 0; c < 4; c++) o[a][c] = 0.f;
    float m[2] = {-1e30f, -1e30f};
    float lsum[2] = {0.f, 0.f};

    const int NT = SEQ / 128;
    attn_load_stage(sb, qk_base, 0);
    CP_COMMIT();

    for (int t = 0; t < NT; t++) {
        if (t + 1 < NT) {
            attn_load_stage(sb + ((t + 1) & 1) * A_STAGE, qk_base, t + 1);
            CP_COMMIT();
            CP_WAIT(1);
        } else {
            CP_WAIT(0);
        }
        __syncthreads();
        const uint32_t st = sb + (t & 1) * A_STAGE;

        // S = Q K^T (bf16x3), rows warp*16..+15, all 128 key cols
        float sc[16][4];
        #pragma unroll
        for (int a = 0; a < 16; a++)
            #pragma unroll
            for (int c = 0; c < 4; c++) sc[a][c] = 0.f;

        #pragma unroll
        for (int kk = 0; kk < 4; kk++) {
            #pragma unroll
            for (int njp = 0; njp < 8; njp++) {
                uint32_t bh4[4], bl4[4];
                ldsm4(b_addr(st + A_KH, njp * 16, kk * 16, lane, GSTR), bh4[0], bh4[1], bh4[2], bh4[3]);
                ldsm4(b_addr(st + A_KL, njp * 16, kk * 16, lane, GSTR), bl4[0], bl4[1], bl4[2], bl4[3]);
                float* c0 = sc[2 * njp];
                float* c1 = sc[2 * njp + 1];
                mma16816(c0, qh[kk][0], qh[kk][1], qh[kk][2], qh[kk][3], bh4[0], bh4[1]);
                mma16816(c0, ql[kk][0], ql[kk][1], ql[kk][2], ql[kk][3], bh4[0], bh4[1]);
                mma16816(c0, qh[kk][0], qh[kk][1], qh[kk][2], qh[kk][3], bl4[0], bl4[1]);
                mma16816(c1, qh[kk][0], qh[kk][1], qh[kk][2], qh[kk][3], bh4[2], bh4[3]);
                mma16816(c1, ql[kk][0], ql[kk][1], ql[kk][2], ql[kk][3], bh4[2], bh4[3]);
                mma16816(c1, qh[kk][0], qh[kk][1], qh[kk][2], qh[kk][3], bl4[2], bl4[3]);
            }
        }

        // online softmax; rows r = lane>>2 (ri=0) and r+8 (ri=1)
        float mx[2] = {-1e30f, -1e30f};
        #pragma unroll
        for (int nj = 0; nj < 16; nj++) {
            mx[0] = fmaxf(mx[0], fmaxf(sc[nj][0], sc[nj][1]));
            mx[1] = fmaxf(mx[1], fmaxf(sc[nj][2], sc[nj][3]));
        }
        #pragma unroll
        for (int ri = 0; ri < 2; ri++) {
            mx[ri] = fmaxf(mx[ri], __shfl_xor_sync(0xffffffff, mx[ri], 1));
            mx[ri] = fmaxf(mx[ri], __shfl_xor_sync(0xffffffff, mx[ri], 2));
        }
        float corr[2];
        #pragma unroll
        for (int ri = 0; ri < 2; ri++) {
            float nm = fmaxf(m[ri], mx[ri]);
            corr[ri] = __expf(m[ri] - nm);
            m[ri] = nm;
        }

        // exp + split into register A-fragments (validated path, R3==R4)
        float ls[2] = {0.f, 0.f};
        uint32_t ph[16][2], pl[16][2];
        #pragma unroll
        for (int nj = 0; nj < 16; nj++) {
            float p0 = __expf(sc[nj][0] - m[0]);
            float p1 = __expf(sc[nj][1] - m[0]);
            float p2 = __expf(sc[nj][2] - m[1]);
            float p3 = __expf(sc[nj][3] - m[1]);
            ls[0] += p0 + p1; ls[1] += p2 + p3;
            __nv_bfloat16 a0, b0, a1, b1, a2, b2, a3, b3;
            split2(p0, a0, b0); split2(p1, a1, b1);
            split2(p2, a2, b2); split2(p3, a3, b3);
            ph[nj][0] = pack2(a0, a1); pl[nj][0] = pack2(b0, b1);
            ph[nj][1] = pack2(a2, a3); pl[nj][1] = pack2(b2, b3);
        }
        // quad-reduce the row sums (each lane holds 32/128 cols)
        #pragma unroll
        for (int ri = 0; ri < 2; ri++) {
            ls[ri] += __shfl_xor_sync(0xffffffff, ls[ri], 1);
            ls[ri] += __shfl_xor_sync(0xffffffff, ls[ri], 2);
        }
        lsum[0] = lsum[0] * corr[0] + ls[0];
        lsum[1] = lsum[1] * corr[1] + ls[1];
        #pragma unroll
        for (int nj = 0; nj < 8; nj++) {
            o[nj][0] *= corr[0]; o[nj][1] *= corr[0];
            o[nj][2] *= corr[1]; o[nj][3] *= corr[1];
        }

        // O += P V (bf16x3): A frags directly from registers
        #pragma unroll
        for (int kk = 0; kk < 8; kk++) {
            uint32_t a0h = ph[2 * kk][0],     a1h = ph[2 * kk][1];
            uint32_t a2h = ph[2 * kk + 1][0], a3h = ph[2 * kk + 1][1];
            uint32_t a0l = pl[2 * kk][0],     a1l = pl[2 * kk][1];
            uint32_t a2l = pl[2 * kk + 1][0], a3l = pl[2 * kk + 1][1];
            #pragma unroll
            for (int njp = 0; njp < 4; njp++) {
                uint32_t bh4[4], bl4[4];
                ldsm4(b_addr(st + A_VH, njp * 16, kk * 16, lane, VSTR), bh4[0], bh4[1], bh4[2], bh4[3]);
                ldsm4(b_addr(st + A_VL, njp * 16, kk * 16, lane, VSTR), bl4[0], bl4[1], bl4[2], bl4[3]);
                float* c0 = o[2 * njp];
                float* c1 = o[2 * njp + 1];
                mma16816(c0, a0h, a1h, a2h, a3h, bh4[0], bh4[1]);
                mma16816(c0, a0l, a1l, a2l, a3l, bh4[0], bh4[1]);
                mma16816(c0, a0h, a1h, a2h, a3h, bl4[0], bl4[1]);
                mma16816(c1, a0h, a1h, a2h, a3h, bh4[2], bh4[3]);
                mma16816(c1, a0l, a1l, a2l, a3l, bh4[2], bh4[3]);
                mma16816(c1, a0h, a1h, a2h, a3h, bl4[2], bl4[3]);
            }
        }
        __syncthreads();  // done reading stage t before its buffer is re-filled
    }

    // epilogue: normalize + split-write to g_Ah/g_Al
    const int b = bh >> 3, h = bh & 7;
    float inv[2] = {1.f / lsum[0], 1.f / lsum[1]};
    #pragma unroll
    for (int ri = 0; ri < 2; ri++) {
        int r = q0 + warp * 16 + (lane >> 2) + ri * 8;
        size_t R = (size_t)(b * SEQ + r) * EMB + h * HDIM;
        #pragma unroll
        for (int nj = 0; nj < 8; nj++) {
            int dd = nj * 8 + (lane & 3) * 2;
            float v0 = o[nj][ri * 2 + 0] * inv[ri];
            float v1 = o[nj][ri * 2 + 1] * inv[ri];
            __nv_bfloat16 h0, l0, h1, l1;
            split2(v0, h0, l0); split2(v1, h1, l1);
            *(uint32_t*)(g_Ah + R + dd) = pack2(h0, h1);
            *(uint32_t*)(g_Al + R + dd) = pack2(l0, l1);
        }
    }
}

// ---------------------------------------------------------------------------
extern "C" void kernel_launch(void* const* d_in, const int* in_sizes, int n_in,
                              void* d_out, int out_size)
{
    const float* x     = (const float*)d_in[0];
    const float* w_qkv = (const float*)d_in[1];
    const float* w_o   = (const float*)d_in[2];
    const float* b_o   = (const float*)d_in[3];
    float* out = (float*)d_out;

    cudaFuncSetAttribute(gemm_qkv_tc, cudaFuncAttributeMaxDynamicSharedMemorySize, G_SMEM_SZ);
    cudaFuncSetAttribute(gemm_out_tc, cudaFuncAttributeMaxDynamicSharedMemorySize, G_SMEM_SZ);
    cudaFuncSetAttribute(attn_tc,     cudaFuncAttributeMaxDynamicSharedMemorySize, A_SMEM_SZ);

    __nv_bfloat16 *xh, *xl, *wqh, *wql, *woh, *wol;
    cudaGetSymbolAddress((void**)&xh,  g_Xh);  cudaGetSymbolAddress((void**)&xl,  g_Xl);
    cudaGetSymbolAddress((void**)&wqh, g_Wqh); cudaGetSymbolAddress((void**)&wql, g_Wql);
    cudaGetSymbolAddress((void**)&woh, g_Woh); cudaGetSymbolAddress((void**)&wol, g_Wol);

    split_kernel<<<(M1 * KD + 255) / 256, 256>>>(x, xh, xl, M1 * KD);
    tsplit_kernel<<<(KD * N1 + 255) / 256, 256>>>(w_qkv, wqh, wql, KD, N1);
    tsplit_kernel<<<(KD * EMB + 255) / 256, 256>>>(w_o, woh, wol, KD, EMB);

    gemm_qkv_tc<<<dim3(N1 / 128, M1 / 128), 256, G_SMEM_SZ>>>();
    attn_tc<<<dim3(SEQ / 128, BATCH * NHEAD), 256, A_SMEM_SZ>>>();
    gemm_out_tc<<<dim3(EMB / 128, M1 / 128), 256, G_SMEM_SZ>>>(b_o, out);
}